// round 1
// baseline (speedup 1.0000x reference)
#include <cuda_runtime.h>
#include <math.h>

// Problem constants
#define NUM_B 2
#define NUM_C 256
#define IMG_H 96
#define IMG_W 320
#define NUM_L 128
#define NUM_WG 128
#define NLAYER 5
#define NQ (NUM_L * NUM_WG)      // 16384
#define NM (NUM_B * NQ)          // 32768
#define NK (NUM_C * NLAYER)      // 1280
#define HW (IMG_H * IMG_W)       // 30720
#define NROWS (NUM_B * NUM_C * IMG_H)     // 49152
#define NCOLT (NUM_B * NUM_C * IMG_W)     // 163840
#define NBOX (NUM_B * NLAYER * NQ)        // 163840

// Scratch (device globals: allocation-free per harness rules)
__device__ float  g_rowcum[NUM_B * NUM_C * IMG_H * IMG_W];     // 63MB
__device__ float  g_itrans[NUM_B * IMG_H * IMG_W * NUM_C];     // 63MB, [b][y][x][c]
__device__ float  g_vox[41943040];                             // 167MB, [m][layer*256+c]
__device__ float  g_wperm[NUM_C * NK];                         // 1.3MB, [co][layer*256+c]
__device__ int4   g_bpi[NBOX];     // x0min, x0max, y0min, y0max
__device__ float4 g_bpw[NBOX];     // wx1min, wx1max, wy1min, wy1max
__device__ float  g_bpa[NBOX];     // visible ? 1/area : 0

// ---------------- K1: row cumsum (sequential, matches reference order) ----------------
__global__ void k_rowcum(const float* __restrict__ feat) {
    int r = blockIdx.x * blockDim.x + threadIdx.x;
    if (r >= NROWS) return;
    const float* src = feat + (size_t)r * IMG_W;
    float* dst = g_rowcum + (size_t)r * IMG_W;
    float acc = 0.0f;
    #pragma unroll 8
    for (int x = 0; x < IMG_W; ++x) {
        acc += src[x];
        dst[x] = acc;
    }
}

// ---------------- K2: column cumsum + transpose to [b][y][x][c] ----------------
__global__ void k_colcum_t() {
    int t = blockIdx.x * blockDim.x + threadIdx.x;
    if (t >= NCOLT) return;
    int x = t % IMG_W;
    int c = (t / IMG_W) % NUM_C;
    int b = t / (IMG_W * NUM_C);
    const float* src = g_rowcum + ((size_t)(b * NUM_C + c) * IMG_H) * IMG_W + x;
    float* dst = g_itrans + (size_t)b * HW * NUM_C + (size_t)x * NUM_C + c;
    float acc = 0.0f;
    for (int y = 0; y < IMG_H; ++y) {
        acc += src[(size_t)y * IMG_W];
        dst[(size_t)y * IMG_W * NUM_C] = acc;
    }
}

// ---------------- K3: project cube corners -> box params ----------------
__global__ void k_boxes(const float* __restrict__ calib, const float* __restrict__ grid) {
    int i = blockIdx.x * blockDim.x + threadIdx.x;
    if (i >= NBOX) return;
    int q = i % NQ;
    int layer = (i / NQ) % NLAYER;
    int b = i / (NQ * NLAYER);

    float gx = grid[q * 3 + 0];
    float gy = grid[q * 3 + 1];
    float gz = grid[q * 3 + 2] + 32.0f * (float)layer;

    const float* M = calib + b * 12;
    float m00 = M[0], m01 = M[1], m02 = M[2],  m03 = M[3];
    float m10 = M[4], m11 = M[5], m12 = M[6],  m13 = M[7];
    float m20 = M[8], m21 = M[9], m22 = M[10], m23 = M[11];

    const float ox[8] = {-12.5f, 12.5f, 12.5f, -12.5f, -12.5f, 12.5f, 12.5f, -12.5f};
    const float oy[8] = {-12.5f, -12.5f, 12.5f, 12.5f, -12.5f, -12.5f, 12.5f, 12.5f};
    const float oz[8] = {0.0f, 0.0f, 0.0f, 0.0f, 32.0f, 32.0f, 32.0f, 32.0f};

    float mnx = 1e30f, mny = 1e30f, mxx = -1e30f, mxy = -1e30f;
    #pragma unroll
    for (int k = 0; k < 8; ++k) {
        float X = gx + ox[k];
        float Y = gy + oy[k];
        float Z = gz + oz[k];
        float px = m00 * X + m01 * Y + m02 * Z + m03;
        float py = m10 * X + m11 * Y + m12 * Z + m13;
        float pz = m20 * X + m21 * Y + m22 * Z + m23;
        float zc = fmaxf(pz, 1e-6f);
        float ix = px / zc;
        float iy = py / zc;
        float nx = fminf(fmaxf(2.0f * ix / 320.0f - 1.0f, -1.0f), 0.95f);
        float ny = fminf(fmaxf(2.0f * iy / 96.0f - 1.0f, -1.0f), 0.95f);
        mnx = fminf(mnx, nx);
        mny = fminf(mny, ny);
        mxx = fmaxf(mxx, nx);
        mxy = fmaxf(mxy, ny);
    }

    float area = ((mxx - mnx) * (mxy - mny)) * (float)HW + 1e-6f;
    bool visible = (area > 1e-6f) && (area < (float)HW * 0.3f);

    // grid_sample coordinates (align_corners=False style)
    float xs1 = ((mnx + 1.0f) * 320.0f - 1.0f) * 0.5f;
    float xs2 = ((mxx + 1.0f) * 320.0f - 1.0f) * 0.5f;
    float ys1 = ((mny + 1.0f) * 96.0f - 1.0f) * 0.5f;
    float ys2 = ((mxy + 1.0f) * 96.0f - 1.0f) * 0.5f;
    float fx1 = floorf(xs1), fx2 = floorf(xs2);
    float fy1 = floorf(ys1), fy2 = floorf(ys2);

    g_bpi[i] = make_int4((int)fx1, (int)fx2, (int)fy1, (int)fy2);
    g_bpw[i] = make_float4(xs1 - fx1, xs2 - fx2, ys1 - fy1, ys2 - fy2);
    g_bpa[i] = visible ? (1.0f / area) : 0.0f;
}

// ---------------- K4: box-filter sampling -> vox ----------------
__device__ __forceinline__ float tapv(const float* __restrict__ I, int X, int Y) {
    if ((unsigned)X < (unsigned)IMG_W && (unsigned)Y < (unsigned)IMG_H)
        return I[((size_t)Y * IMG_W + X) * NUM_C];
    return 0.0f;
}

__global__ void k_sample() {
    int m = blockIdx.x;          // 0..32767
    int c = threadIdx.x;         // 0..255
    int b = m >> 14;
    int q = m & (NQ - 1);
    const float* I = g_itrans + (size_t)b * HW * NUM_C + c;
    float* vdst = g_vox + (size_t)m * NK;

    for (int layer = 0; layer < NLAYER; ++layer) {
        int i = (b * NLAYER + layer) * NQ + q;
        float inv = g_bpa[i];
        float v = 0.0f;
        if (inv != 0.0f) {
            int4 xi = g_bpi[i];
            float4 wf = g_bpw[i];
            int x1 = xi.x, x2 = xi.y, y1 = xi.z, y2 = xi.w;
            float wx1m = wf.x, wx1M = wf.y, wy1m = wf.z, wy1M = wf.w;
            float wx0m = 1.0f - wx1m, wx0M = 1.0f - wx1M;
            float wy0m = 1.0f - wy1m, wy0M = 1.0f - wy1M;

            float lt = tapv(I, x1,     y1) * (wx0m * wy0m)
                     + tapv(I, x1 + 1, y1) * (wx1m * wy0m)
                     + tapv(I, x1,     y1 + 1) * (wx0m * wy1m)
                     + tapv(I, x1 + 1, y1 + 1) * (wx1m * wy1m);
            float rb = tapv(I, x2,     y2) * (wx0M * wy0M)
                     + tapv(I, x2 + 1, y2) * (wx1M * wy0M)
                     + tapv(I, x2,     y2 + 1) * (wx0M * wy1M)
                     + tapv(I, x2 + 1, y2 + 1) * (wx1M * wy1M);
            float rt = tapv(I, x2,     y1) * (wx0M * wy0m)
                     + tapv(I, x2 + 1, y1) * (wx1M * wy0m)
                     + tapv(I, x2,     y1 + 1) * (wx0M * wy1m)
                     + tapv(I, x2 + 1, y1 + 1) * (wx1M * wy1m);
            float lb = tapv(I, x1,     y2) * (wx0m * wy0M)
                     + tapv(I, x1 + 1, y2) * (wx1m * wy0M)
                     + tapv(I, x1,     y2 + 1) * (wx0m * wy1M)
                     + tapv(I, x1 + 1, y2 + 1) * (wx1m * wy1M);
            v = (((lt + rb) - rt) - lb) * inv;
        }
        vdst[layer * NUM_C + c] = v;
    }
}

// ---------------- K5: permute Wc to K-order layer*256+c ----------------
__global__ void k_wperm(const float* __restrict__ Wc) {
    int idx = blockIdx.x * blockDim.x + threadIdx.x;
    if (idx >= NUM_C * NK) return;
    int co = idx / NK;
    int kd = idx % NK;
    int layer = kd / NUM_C;
    int c = kd % NUM_C;
    g_wperm[idx] = Wc[co * NK + c * NLAYER + layer];
}

// ---------------- K6: GEMM (M=32768,N=256,K=1280) + bias + relu, fma.rn.f32x2 ----------------
__global__ __launch_bounds__(256) void k_gemm(const float* __restrict__ bc, float* __restrict__ out) {
    __shared__ float As[8][128];
    __shared__ float Bs[8][128];

    int m0 = blockIdx.x * 128;
    int n0 = blockIdx.y * 128;
    int tid = threadIdx.x;
    int row = tid >> 1;
    int half = tid & 1;
    int tm = tid & 15;    // M micro index
    int tn = tid >> 4;    // N micro index

    const float4* aptr = (const float4*)(g_vox + (size_t)(m0 + row) * NK + half * 4);
    const float4* bptr = (const float4*)(g_wperm + (size_t)(n0 + row) * NK + half * 4);

    unsigned long long acc[8][4];
    #pragma unroll
    for (int i = 0; i < 8; ++i)
        #pragma unroll
        for (int j = 0; j < 4; ++j) acc[i][j] = 0ULL;

    float4 ra = aptr[0];
    float4 rb = bptr[0];

    for (int kt = 0; kt < NK / 8; ++kt) {
        int kc = half * 4;
        As[kc + 0][row] = ra.x; As[kc + 1][row] = ra.y;
        As[kc + 2][row] = ra.z; As[kc + 3][row] = ra.w;
        Bs[kc + 0][row] = rb.x; Bs[kc + 1][row] = rb.y;
        Bs[kc + 2][row] = rb.z; Bs[kc + 3][row] = rb.w;
        __syncthreads();
        if (kt < NK / 8 - 1) {
            ra = aptr[(kt + 1) * 2];
            rb = bptr[(kt + 1) * 2];
        }
        #pragma unroll
        for (int kk = 0; kk < 8; ++kk) {
            float4 a4a = *(const float4*)&As[kk][tm * 8];
            float4 a4b = *(const float4*)&As[kk][tm * 8 + 4];
            unsigned long long a2[8];
            {
                unsigned u;
                u = __float_as_uint(a4a.x); asm("mov.b64 %0, {%1,%1};" : "=l"(a2[0]) : "r"(u));
                u = __float_as_uint(a4a.y); asm("mov.b64 %0, {%1,%1};" : "=l"(a2[1]) : "r"(u));
                u = __float_as_uint(a4a.z); asm("mov.b64 %0, {%1,%1};" : "=l"(a2[2]) : "r"(u));
                u = __float_as_uint(a4a.w); asm("mov.b64 %0, {%1,%1};" : "=l"(a2[3]) : "r"(u));
                u = __float_as_uint(a4b.x); asm("mov.b64 %0, {%1,%1};" : "=l"(a2[4]) : "r"(u));
                u = __float_as_uint(a4b.y); asm("mov.b64 %0, {%1,%1};" : "=l"(a2[5]) : "r"(u));
                u = __float_as_uint(a4b.z); asm("mov.b64 %0, {%1,%1};" : "=l"(a2[6]) : "r"(u));
                u = __float_as_uint(a4b.w); asm("mov.b64 %0, {%1,%1};" : "=l"(a2[7]) : "r"(u));
            }
            #pragma unroll
            for (int j = 0; j < 4; ++j) {
                unsigned long long b2 = *(const unsigned long long*)&Bs[kk][tn * 8 + j * 2];
                #pragma unroll
                for (int i = 0; i < 8; ++i)
                    asm("fma.rn.f32x2 %0, %1, %2, %0;" : "+l"(acc[i][j]) : "l"(a2[i]), "l"(b2));
            }
        }
        __syncthreads();
    }

    // Epilogue: out[b][co][q] = relu(acc + bc[co])
    #pragma unroll
    for (int i = 0; i < 8; ++i) {
        int m = m0 + tm * 8 + i;
        int bb = m >> 14;
        int q = m & (NQ - 1);
        float* obase = out + (size_t)bb * ((size_t)NUM_C * NQ) + q;
        #pragma unroll
        for (int j = 0; j < 4; ++j) {
            int n = n0 + tn * 8 + j * 2;
            float vlo = __uint_as_float((unsigned)(acc[i][j])) + bc[n];
            float vhi = __uint_as_float((unsigned)(acc[i][j] >> 32)) + bc[n + 1];
            obase[(size_t)n * NQ] = fmaxf(vlo, 0.0f);
            obase[(size_t)(n + 1) * NQ] = fmaxf(vhi, 0.0f);
        }
    }
}

extern "C" void kernel_launch(void* const* d_in, const int* in_sizes, int n_in,
                              void* d_out, int out_size) {
    const float* feature = (const float*)d_in[0];  // (2,256,96,320)
    const float* calib   = (const float*)d_in[1];  // (2,3,4)
    const float* grid    = (const float*)d_in[2];  // (128,128,3)
    const float* Wc      = (const float*)d_in[3];  // (256,1280)
    const float* bc      = (const float*)d_in[4];  // (256,)
    float* out = (float*)d_out;                    // (2,256,128,128)

    k_rowcum<<<(NROWS + 255) / 256, 256>>>(feature);
    k_colcum_t<<<(NCOLT + 255) / 256, 256>>>();
    k_boxes<<<(NBOX + 255) / 256, 256>>>(calib, grid);
    k_sample<<<NM, NUM_C>>>();
    k_wperm<<<(NUM_C * NK + 255) / 256, 256>>>(Wc);
    {
        dim3 g(NM / 128, NUM_C / 128);
        k_gemm<<<g, 256>>>(bc, out);
    }
}

// round 3
// speedup vs baseline: 2.9971x; 2.9971x over previous
#include <cuda_runtime.h>
#include <math.h>
#include <stdint.h>

// Problem constants
#define NUM_B 2
#define NUM_C 256
#define IMG_H 96
#define IMG_W 320
#define NLAYER 5
#define NQ (128 * 128)           // 16384
#define NM (NUM_B * NQ)          // 32768
#define NK (NUM_C * NLAYER)      // 1280
#define HW (IMG_H * IMG_W)       // 30720
#define NROWS (NUM_B * NUM_C * IMG_H)     // 49152
#define NBOX (NUM_B * NLAYER * NQ)        // 163840

// Scratch (device globals: allocation-free per harness rules)
__device__ float  g_rowcum[NUM_B * NUM_C * IMG_H * IMG_W];     // 63MB
__device__ float  g_itrans[NUM_B * IMG_H * IMG_W * NUM_C];     // 63MB, [b][y][x][c]
__device__ float  g_vox[NM * NK];                              // 168MB, [m][layer*256+c], tf32-rounded
__device__ float  g_wperm[NUM_C * NK];                         // 1.3MB, [co][layer*256+c], tf32-rounded
__device__ float  g_bpa[NBOX];                                 // visible ? 1/area : 0
__device__ int2   g_tap[NBOX * 16];                            // {pixel idx, weight bits}

__device__ __forceinline__ float tf32r(float v) {
    uint32_t o;
    asm("cvt.rna.tf32.f32 %0, %1;" : "=r"(o) : "f"(v));
    return __uint_as_float(o);
}

// ---------------- K1: row cumsum, warp-per-row shfl scan ----------------
__global__ void k_rowcum(const float* __restrict__ feat) {
    int w = (blockIdx.x * blockDim.x + threadIdx.x) >> 5;
    int lane = threadIdx.x & 31;
    if (w >= NROWS) return;
    const float* src = feat + (size_t)w * IMG_W;
    float* dst = g_rowcum + (size_t)w * IMG_W;
    float carry = 0.0f;
    #pragma unroll
    for (int c0 = 0; c0 < IMG_W; c0 += 32) {
        float v = src[c0 + lane];
        #pragma unroll
        for (int d = 1; d < 32; d <<= 1) {
            float n = __shfl_up_sync(0xFFFFFFFFu, v, d);
            if (lane >= d) v += n;
        }
        v += carry;
        dst[c0 + lane] = v;
        carry = __shfl_sync(0xFFFFFFFFu, v, 31);
    }
}

// ---------------- K2: column cumsum + transpose to [b][y][x][c], tiled ----------------
__global__ void k_colcum_t() {
    __shared__ float tile[32][33];
    int x0 = blockIdx.x * 32;
    int c0 = blockIdx.y * 32;
    int b  = blockIdx.z;
    int tx = threadIdx.x, ty = threadIdx.y;
    const float* src = g_rowcum + ((size_t)(b * NUM_C + c0 + ty) * IMG_H) * IMG_W + x0 + tx;
    float* dstbase = g_itrans + (size_t)b * HW * NUM_C;
    float acc = 0.0f;
    for (int y = 0; y < IMG_H; ++y) {
        acc += src[(size_t)y * IMG_W];
        tile[ty][tx] = acc;
        __syncthreads();
        dstbase[((size_t)y * IMG_W + x0 + ty) * NUM_C + c0 + tx] = tile[tx][ty];
        __syncthreads();
    }
}

// ---------------- K3: project corners -> per-box tap table ----------------
__global__ void k_boxes(const float* __restrict__ calib, const float* __restrict__ grid) {
    int i = blockIdx.x * blockDim.x + threadIdx.x;
    if (i >= NBOX) return;
    int q = i % NQ;
    int layer = (i / NQ) % NLAYER;
    int b = i / (NQ * NLAYER);

    float gx = grid[q * 3 + 0];
    float gy = grid[q * 3 + 1];
    float gz = grid[q * 3 + 2] + 32.0f * (float)layer;

    const float* M = calib + b * 12;
    float m00 = M[0], m01 = M[1], m02 = M[2],  m03 = M[3];
    float m10 = M[4], m11 = M[5], m12 = M[6],  m13 = M[7];
    float m20 = M[8], m21 = M[9], m22 = M[10], m23 = M[11];

    const float ox[8] = {-12.5f, 12.5f, 12.5f, -12.5f, -12.5f, 12.5f, 12.5f, -12.5f};
    const float oy[8] = {-12.5f, -12.5f, 12.5f, 12.5f, -12.5f, -12.5f, 12.5f, 12.5f};
    const float oz[8] = {0.0f, 0.0f, 0.0f, 0.0f, 32.0f, 32.0f, 32.0f, 32.0f};

    float mnx = 1e30f, mny = 1e30f, mxx = -1e30f, mxy = -1e30f;
    #pragma unroll
    for (int k = 0; k < 8; ++k) {
        float X = gx + ox[k];
        float Y = gy + oy[k];
        float Z = gz + oz[k];
        float px = m00 * X + m01 * Y + m02 * Z + m03;
        float py = m10 * X + m11 * Y + m12 * Z + m13;
        float pz = m20 * X + m21 * Y + m22 * Z + m23;
        float zc = fmaxf(pz, 1e-6f);
        float ix = px / zc;
        float iy = py / zc;
        float nx = fminf(fmaxf(2.0f * ix / 320.0f - 1.0f, -1.0f), 0.95f);
        float ny = fminf(fmaxf(2.0f * iy / 96.0f - 1.0f, -1.0f), 0.95f);
        mnx = fminf(mnx, nx);
        mny = fminf(mny, ny);
        mxx = fmaxf(mxx, nx);
        mxy = fmaxf(mxy, ny);
    }

    float area = ((mxx - mnx) * (mxy - mny)) * (float)HW + 1e-6f;
    bool visible = (area > 1e-6f) && (area < (float)HW * 0.3f);
    float inv = visible ? (1.0f / area) : 0.0f;
    g_bpa[i] = inv;
    if (!visible) return;

    float xs[2], ys[2];
    xs[0] = ((mnx + 1.0f) * 320.0f - 1.0f) * 0.5f;
    xs[1] = ((mxx + 1.0f) * 320.0f - 1.0f) * 0.5f;
    ys[0] = ((mny + 1.0f) * 96.0f - 1.0f) * 0.5f;
    ys[1] = ((mxy + 1.0f) * 96.0f - 1.0f) * 0.5f;

    // corners: lt(min,min,+), rb(max,max,+), rt(max,min,-), lb(min,max,-)
    const int cxi[4] = {0, 1, 1, 0};
    const int cyi[4] = {0, 1, 0, 1};
    const float csg[4] = {1.0f, 1.0f, -1.0f, -1.0f};
    int2* tp = g_tap + (size_t)i * 16;
    #pragma unroll
    for (int cc = 0; cc < 4; ++cc) {
        float sx = xs[cxi[cc]], sy = ys[cyi[cc]];
        float fx = floorf(sx), fy = floorf(sy);
        int x0 = (int)fx, y0 = (int)fy;
        float wx1 = sx - fx, wy1 = sy - fy;
        float wx0 = 1.0f - wx1, wy0 = 1.0f - wy1;
        float s = csg[cc] * inv;
        #pragma unroll
        for (int tt = 0; tt < 4; ++tt) {
            int xi = x0 + (tt & 1);
            int yi = y0 + (tt >> 1);
            float w = ((tt & 1) ? wx1 : wx0) * ((tt >> 1) ? wy1 : wy0) * s;
            bool valid = ((unsigned)xi < (unsigned)IMG_W) && ((unsigned)yi < (unsigned)IMG_H);
            int idx = valid ? (yi * IMG_W + xi) : 0;
            if (!valid) w = 0.0f;
            tp[cc * 4 + tt] = make_int2(idx, __float_as_int(w));
        }
    }
}

// ---------------- K4: box-filter sampling -> vox (tf32-rounded) ----------------
__global__ void k_sample() {
    int m = blockIdx.x;
    int c = threadIdx.x;
    int b = m >> 14;
    int q = m & (NQ - 1);
    const float* I = g_itrans + (size_t)b * HW * NUM_C + c;
    float* vdst = g_vox + (size_t)m * NK;

    #pragma unroll
    for (int layer = 0; layer < NLAYER; ++layer) {
        int i = (b * NLAYER + layer) * NQ + q;
        float inv = g_bpa[i];
        float v = 0.0f;
        if (inv != 0.0f) {
            const int2* tp = g_tap + (size_t)i * 16;
            #pragma unroll
            for (int t = 0; t < 16; ++t) {
                int2 tw = __ldg(tp + t);
                v = fmaf(I[(size_t)tw.x * NUM_C], __int_as_float(tw.y), v);
            }
        }
        vdst[layer * NUM_C + c] = tf32r(v);
    }
}

// ---------------- K5: permute Wc to K-order layer*256+c (tf32-rounded) ----------------
__global__ void k_wperm(const float* __restrict__ Wc) {
    int idx = blockIdx.x * blockDim.x + threadIdx.x;
    if (idx >= NUM_C * NK) return;
    int co = idx / NK;
    int kd = idx % NK;
    int layer = kd / NUM_C;
    int c = kd % NUM_C;
    g_wperm[idx] = tf32r(Wc[co * NK + c * NLAYER + layer]);
}

// ---------------- K6: mma.sync tf32 GEMM (M=32768,N=256,K=1280) + bias + relu ----------------
// CTA tile 128(M)x128(N), 8 warps as 4(M)x2(N), warp tile 32x64.
// K-chunk 32, double-buffered smem via cp.async. Smem rows padded to 36 floats.
#define KC 32
#define NKT (NK / KC)            // 40
#define SM_ROW 36
#define SM_TILE (128 * SM_ROW)   // floats per A or B buffer (4608)
#define SM_STAGE (2 * SM_TILE)   // A + B (9216 floats)
#define GSM_BYTES (2 * SM_STAGE * 4)   // 73728

__device__ __forceinline__ void cp16(uint32_t saddr, const void* gptr) {
    asm volatile("cp.async.cg.shared.global [%0], [%1], 16;" :: "r"(saddr), "l"(gptr) : "memory");
}
__device__ __forceinline__ uint32_t smem_u32(const void* p) {
    uint32_t a;
    asm("{ .reg .u64 t; cvta.to.shared.u64 t, %1; cvt.u32.u64 %0, t; }" : "=r"(a) : "l"(p));
    return a;
}
__device__ __forceinline__ void mma_tf32(float c[4], uint32_t a0, uint32_t a1, uint32_t a2,
                                         uint32_t a3, uint32_t b0, uint32_t b1) {
    asm volatile(
        "mma.sync.aligned.m16n8k8.row.col.f32.tf32.tf32.f32 "
        "{%0,%1,%2,%3}, {%4,%5,%6,%7}, {%8,%9}, {%0,%1,%2,%3};"
        : "+f"(c[0]), "+f"(c[1]), "+f"(c[2]), "+f"(c[3])
        : "r"(a0), "r"(a1), "r"(a2), "r"(a3), "r"(b0), "r"(b1));
}

__global__ __launch_bounds__(256) void k_gemm(const float* __restrict__ bc,
                                              float* __restrict__ out) {
    extern __shared__ float smf[];
    uint32_t smb = smem_u32(smf);
    int tid = threadIdx.x;
    int wid = tid >> 5;
    int lane = tid & 31;
    int g = lane >> 2;        // group id 0..7
    int tg = lane & 3;        // thread in group
    int wm = wid & 3;         // warp M index (0..3)
    int wn = wid >> 2;        // warp N index (0..1)
    int n0 = blockIdx.x * 128;
    int m0 = blockIdx.y * 128;

    // Loader mapping: kq = tid&7, rowoff = tid>>3 (+32 per r)
    int kq = tid & 7;
    int rbase = tid >> 3;

    float acc[2][8][4];
    #pragma unroll
    for (int mi = 0; mi < 2; ++mi)
        #pragma unroll
        for (int nj = 0; nj < 8; ++nj)
            #pragma unroll
            for (int cc = 0; cc < 4; ++cc) acc[mi][nj][cc] = 0.0f;

    // prologue: load kt=0 into stage 0
    {
        #pragma unroll
        for (int r = 0; r < 4; ++r) {
            int row = r * 32 + rbase;
            uint32_t sa = smb + (uint32_t)((row * SM_ROW + kq * 4) * 4);
            cp16(sa, g_vox + (size_t)(m0 + row) * NK + kq * 4);
            uint32_t sb = smb + (uint32_t)((SM_TILE + row * SM_ROW + kq * 4) * 4);
            cp16(sb, g_wperm + (size_t)(n0 + row) * NK + kq * 4);
        }
        asm volatile("cp.async.commit_group;" ::: "memory");
    }

    for (int kt = 0; kt < NKT; ++kt) {
        if (kt + 1 < NKT) {
            uint32_t sbase = smb + (uint32_t)(((kt + 1) & 1) * SM_STAGE * 4);
            int koff = (kt + 1) * KC;
            #pragma unroll
            for (int r = 0; r < 4; ++r) {
                int row = r * 32 + rbase;
                cp16(sbase + (uint32_t)((row * SM_ROW + kq * 4) * 4),
                     g_vox + (size_t)(m0 + row) * NK + koff + kq * 4);
                cp16(sbase + (uint32_t)((SM_TILE + row * SM_ROW + kq * 4) * 4),
                     g_wperm + (size_t)(n0 + row) * NK + koff + kq * 4);
            }
            asm volatile("cp.async.commit_group;" ::: "memory");
            asm volatile("cp.async.wait_group 1;" ::: "memory");
        } else {
            asm volatile("cp.async.wait_group 0;" ::: "memory");
        }
        __syncthreads();

        const float* As = smf + (kt & 1) * SM_STAGE;
        const float* Bs = As + SM_TILE;
        #pragma unroll
        for (int ks = 0; ks < 4; ++ks) {
            int kk = ks * 8 + tg;
            uint32_t a[2][4];
            #pragma unroll
            for (int mi = 0; mi < 2; ++mi) {
                int mr = wm * 32 + mi * 16 + g;
                a[mi][0] = __float_as_uint(As[mr * SM_ROW + kk]);
                a[mi][1] = __float_as_uint(As[(mr + 8) * SM_ROW + kk]);
                a[mi][2] = __float_as_uint(As[mr * SM_ROW + kk + 4]);
                a[mi][3] = __float_as_uint(As[(mr + 8) * SM_ROW + kk + 4]);
            }
            #pragma unroll
            for (int nj = 0; nj < 8; ++nj) {
                int nr = wn * 64 + nj * 8 + g;
                uint32_t b0 = __float_as_uint(Bs[nr * SM_ROW + kk]);
                uint32_t b1 = __float_as_uint(Bs[nr * SM_ROW + kk + 4]);
                mma_tf32(acc[0][nj], a[0][0], a[0][1], a[0][2], a[0][3], b0, b1);
                mma_tf32(acc[1][nj], a[1][0], a[1][1], a[1][2], a[1][3], b0, b1);
            }
        }
        __syncthreads();
    }

    // Epilogue: out[b][n][q] = relu(acc + bc[n]);  m -> (b, q)
    #pragma unroll
    for (int mi = 0; mi < 2; ++mi) {
        int r0 = m0 + wm * 32 + mi * 16 + g;
        #pragma unroll
        for (int half = 0; half < 2; ++half) {
            int m = r0 + half * 8;
            int b = m >> 14;
            int q = m & (NQ - 1);
            float* ob = out + (size_t)b * NUM_C * NQ + q;
            #pragma unroll
            for (int nj = 0; nj < 8; ++nj) {
                int n = n0 + wn * 64 + nj * 8 + tg * 2;
                float v0 = acc[mi][nj][half * 2 + 0] + __ldg(bc + n);
                float v1 = acc[mi][nj][half * 2 + 1] + __ldg(bc + n + 1);
                ob[(size_t)n * NQ] = fmaxf(v0, 0.0f);
                ob[(size_t)(n + 1) * NQ] = fmaxf(v1, 0.0f);
            }
        }
    }
}

extern "C" void kernel_launch(void* const* d_in, const int* in_sizes, int n_in,
                              void* d_out, int out_size) {
    const float* feature = (const float*)d_in[0];  // (2,256,96,320)
    const float* calib   = (const float*)d_in[1];  // (2,3,4)
    const float* grid    = (const float*)d_in[2];  // (128,128,3)
    const float* Wc      = (const float*)d_in[3];  // (256,1280)
    const float* bc      = (const float*)d_in[4];  // (256,)
    float* out = (float*)d_out;                    // (2,256,128,128)

    cudaFuncSetAttribute(k_gemm, cudaFuncAttributeMaxDynamicSharedMemorySize, GSM_BYTES);

    k_rowcum<<<NROWS / 8, 256>>>(feature);
    {
        dim3 g(IMG_W / 32, NUM_C / 32, NUM_B);
        dim3 blk(32, 32);
        k_colcum_t<<<g, blk>>>();
    }
    k_boxes<<<(NBOX + 255) / 256, 256>>>(calib, grid);
    k_sample<<<NM, NUM_C>>>();
    k_wperm<<<(NUM_C * NK + 255) / 256, 256>>>(Wc);
    {
        dim3 gg(NUM_C / 128, NM / 128);
        k_gemm<<<gg, 256, GSM_BYTES>>>(bc, out);
    }
}